// round 5
// baseline (speedup 1.0000x reference)
#include <cuda_runtime.h>
#include <math_constants.h>

// Pooling_21577915695109: out[b,n,:] = max over m of x_pad[b, index[n,m], :]
// x: (4, 50000, 64) fp32, index: (50000, 16) int32 in [0, 50000]; idx==50000 -> zero row.
// (JAX without x64 emits int32 indices despite the dtype=jnp.int64 annotation;
//  the R3 fault pattern confirms the buffer is 4-byte indices.)

constexpr int N_NODES = 50000;
constexpr int M_NEIGH = 16;
constexpr int HID     = 64;

constexpr int THREADS_PER_NODE = 16;   // 16 lanes x float4 = 64 floats = one row
constexpr int NODES_PER_BLOCK  = 16;   // 256 threads / block
constexpr int BLOCK_THREADS    = THREADS_PER_NODE * NODES_PER_BLOCK;

__device__ __forceinline__ float4 fmax4(float4 a, float4 b) {
    return make_float4(fmaxf(a.x, b.x), fmaxf(a.y, b.y),
                       fmaxf(a.z, b.z), fmaxf(a.w, b.w));
}

__global__ __launch_bounds__(BLOCK_THREADS)
void pool_max_kernel(const float* __restrict__ x,
                     const int* __restrict__ index,
                     float* __restrict__ out)
{
    const int lane  = threadIdx.x & (THREADS_PER_NODE - 1);
    const int group = threadIdx.x >> 4;
    const int node  = blockIdx.x * NODES_PER_BLOCK + group;
    if (node >= N_NODES) return;

    // Each lane of the group loads one neighbor index (coalesced 64B per group),
    // then broadcasts within the 16-lane segment per m-step.
    const int my_idx = __ldg(&index[(size_t)node * M_NEIGH + lane]);

    const int col = lane * 4;  // float offset within the 64-float row

    float4 acc0 = make_float4(-CUDART_INF_F, -CUDART_INF_F, -CUDART_INF_F, -CUDART_INF_F);
    float4 acc1 = acc0, acc2 = acc0, acc3 = acc0;

    const float4 zero4 = make_float4(0.f, 0.f, 0.f, 0.f);

    #pragma unroll
    for (int m = 0; m < M_NEIGH; m++) {
        // width=16 shuffle: broadcast index m of this group's node to all 16 lanes
        const int idx = __shfl_sync(0xFFFFFFFFu, my_idx, m, THREADS_PER_NODE);
        // Unsigned compare: any idx outside [0, N_NODES) (incl. the N_NODES
        // sentinel and anything unexpected) takes the zero-row path -> no OOB.
        const bool valid = ((unsigned)idx < (unsigned)N_NODES);

        const size_t base    = (size_t)idx * HID + col;
        const size_t bstride = (size_t)N_NODES * HID;

        float4 v0, v1, v2, v3;
        if (valid) {
            v0 = __ldg((const float4*)(x + base));
            v1 = __ldg((const float4*)(x + base + bstride));
            v2 = __ldg((const float4*)(x + base + 2 * bstride));
            v3 = __ldg((const float4*)(x + base + 3 * bstride));
        } else {
            v0 = v1 = v2 = v3 = zero4;   // padded zero row participates in the max
        }
        acc0 = fmax4(acc0, v0);
        acc1 = fmax4(acc1, v1);
        acc2 = fmax4(acc2, v2);
        acc3 = fmax4(acc3, v3);
    }

    const size_t obase    = (size_t)node * HID + col;
    const size_t obstride = (size_t)N_NODES * HID;
    *(float4*)(out + obase)               = acc0;
    *(float4*)(out + obase + obstride)    = acc1;
    *(float4*)(out + obase + 2*obstride)  = acc2;
    *(float4*)(out + obase + 3*obstride)  = acc3;
}

extern "C" void kernel_launch(void* const* d_in, const int* in_sizes, int n_in,
                              void* d_out, int out_size)
{
    const float* x     = (const float*)d_in[0];  // (4, 50000, 64) fp32
    const int*   index = (const int*)d_in[1];    // (50000, 16) int32
    float*       out   = (float*)d_out;          // (4, 50000, 64) fp32

    const int grid = (N_NODES + NODES_PER_BLOCK - 1) / NODES_PER_BLOCK;  // 3125
    pool_max_kernel<<<grid, BLOCK_THREADS>>>(x, index, out);
}

// round 6
// speedup vs baseline: 1.1057x; 1.1057x over previous
#include <cuda_runtime.h>
#include <math_constants.h>

// Pooling_21577915695109: out[b,n,:] = max over m of x_pad[b, index[n,m], :]
// x: (4, 50000, 64) fp32, index: (50000, 16) int32 in [0, 50000]; idx==50000 -> zero row.
//
// R6 shape: batch split over blockIdx.y (4 accumulators/thread instead of 16,
// 32-bit address math) to lift the register-capped occupancy (44 regs -> ~30)
// and push L2 SOL from 68% toward 90%.

constexpr int N_NODES = 50000;
constexpr int M_NEIGH = 16;
constexpr int HID     = 64;

constexpr int THREADS_PER_NODE = 16;   // 16 lanes x float4 = 64 floats = one row
constexpr int NODES_PER_BLOCK  = 16;   // 256 threads / block
constexpr int BLOCK_THREADS    = THREADS_PER_NODE * NODES_PER_BLOCK;

__device__ __forceinline__ float4 fmax4(float4 a, float4 b) {
    return make_float4(fmaxf(a.x, b.x), fmaxf(a.y, b.y),
                       fmaxf(a.z, b.z), fmaxf(a.w, b.w));
}

__global__ __launch_bounds__(BLOCK_THREADS)
void pool_max_kernel(const float* __restrict__ x,
                     const int* __restrict__ index,
                     float* __restrict__ out)
{
    const int lane  = threadIdx.x & (THREADS_PER_NODE - 1);
    const int group = threadIdx.x >> 4;
    const int node  = blockIdx.x * NODES_PER_BLOCK + group;
    if (node >= N_NODES) return;

    const int batch = blockIdx.y;                       // one batch per block
    const float* __restrict__ xb = x + (size_t)batch * (N_NODES * HID);

    // Each lane of the group loads one neighbor index (coalesced 64B per group),
    // then broadcasts within the 16-lane segment per m-step.
    const int my_idx = __ldg(&index[node * M_NEIGH + lane]);

    const unsigned col = lane * 4u;  // float offset within the 64-float row

    float4 acc = make_float4(-CUDART_INF_F, -CUDART_INF_F, -CUDART_INF_F, -CUDART_INF_F);
    const float4 zero4 = make_float4(0.f, 0.f, 0.f, 0.f);

    #pragma unroll
    for (int m = 0; m < M_NEIGH; m++) {
        // width=16 shuffle: broadcast index m of this group's node to all 16 lanes
        const int idx = __shfl_sync(0xFFFFFFFFu, my_idx, m, THREADS_PER_NODE);
        // Unsigned compare: any idx outside [0, N_NODES) (incl. the N_NODES
        // sentinel) takes the zero-row path -> no OOB possible.
        const bool valid = ((unsigned)idx < (unsigned)N_NODES);

        const unsigned off = (unsigned)idx * HID + col;   // < 3.2M, 32-bit safe

        float4 v = valid ? __ldg((const float4*)(xb + off)) : zero4;
        acc = fmax4(acc, v);
    }

    const size_t obase = (size_t)batch * (N_NODES * HID) + (unsigned)node * HID + col;
    *(float4*)(out + obase) = acc;
}

extern "C" void kernel_launch(void* const* d_in, const int* in_sizes, int n_in,
                              void* d_out, int out_size)
{
    const float* x     = (const float*)d_in[0];  // (4, 50000, 64) fp32
    const int*   index = (const int*)d_in[1];    // (50000, 16) int32
    float*       out   = (float*)d_out;          // (4, 50000, 64) fp32

    dim3 grid((N_NODES + NODES_PER_BLOCK - 1) / NODES_PER_BLOCK, 4);  // 3125 x 4
    pool_max_kernel<<<grid, BLOCK_THREADS>>>(x, index, out);
}